// round 14
// baseline (speedup 1.0000x reference)
#include <cuda_runtime.h>
#include <cuda_bf16.h>
#include <math.h>
#include <cstdint>

// Problem constants (shapes fixed by setup_inputs)
#define NV    4096          // batch per view
#define TWON  8192          // 2N rows total
#define FD    512           // feature dim
#define PD    128           // projection dim
#define NB    (TWON / 128)  // 64 tile-blocks per dimension
#define BN_EPS  1e-5f
#define COS_EPS 1e-8f
// exp(sim/T) = 2^(sim * 10 * log2(e));  zn is pre-scaled by sqrt of this
#define SQRT_EXP_C 3.7982825f          // sqrt(14.426950408889634)
#define LN2F 0.69314718056f
#define N_SIM_CTAS 1056                // sum over bi of ceil((NB-bi)/2)

// Scratch (no allocations allowed -> __device__ globals)
__device__ float g_h[TWON * PD];               // projected pre-BN activations
__device__ __nv_bfloat16 g_znb[TWON * PD];     // sqrt(EXP_C)-scaled normalized rows
__device__ float g_sum[2 * PD];                // per-view per-col sum (zeroed by last CTA)
__device__ float g_sumsq[2 * PD];              // per-view per-col sumsq (zeroed by last CTA)
__device__ float g_rowsum[TWON];               // sum_j S_ij (diag excluded)
__device__ float g_pos[TWON];                  // S_{i, i^NV}
__device__ int   g_ctr;                        // completion ticket (reset by last CTA)

// RNA-rounded tf32 (unbiased)
__device__ __forceinline__ float to_tf32(float x) {
    uint32_t u;
    asm("cvt.rna.tf32.f32 %0, %1;" : "=r"(u) : "f"(x));
    return __uint_as_float(u);
}

__device__ __forceinline__ float ex2(float x) {
    float y;
    asm("ex2.approx.ftz.f32 %0, %1;" : "=f"(y) : "f"(x));
    return y;
}

__device__ __forceinline__ void ldsm_x4(uint32_t* r, uint32_t addr) {
    asm volatile("ldmatrix.sync.aligned.m8n8.x4.shared.b16 {%0,%1,%2,%3}, [%4];"
                 : "=r"(r[0]), "=r"(r[1]), "=r"(r[2]), "=r"(r[3]) : "r"(addr));
}

// ---------------------------------------------------------------------------
// K1: h = concat(x, xt) @ W + b via tf32 mma.sync, fused BN column stats.
// CTA tile 64x128, BK=64, 256 threads; 8 warps = 2(m) x 4(n), warp 32x32.
// ---------------------------------------------------------------------------
#define PAROW 68
#define PBROW 136
#define PROJ_SMEM ((64 * PAROW + 64 * PBROW) * 4)

__global__ __launch_bounds__(256) void k_proj_mma(const float* __restrict__ x,
                                                  const float* __restrict__ xt,
                                                  const float* __restrict__ W,
                                                  const float* __restrict__ bias) {
    extern __shared__ float ps[];
    float* As = ps;                       // [64][PAROW]
    float* Bs = ps + 64 * PAROW;          // [64][PBROW]  ([k][n])
    int tid = threadIdx.x;
    int lane = tid & 31, wid = tid >> 5;
    int g = lane >> 2, tig = lane & 3;
    int m0 = blockIdx.x * 64;
    const float* src = (m0 < NV) ? (x + (size_t)m0 * FD)
                                 : (xt + (size_t)(m0 - NV) * FD);
    int rm = (wid & 1) * 32;              // warp row base (m-local)
    int cn = (wid >> 1) * 32;             // warp col base (n-local)

    float acc[2][4][4] = {};

    for (int k0 = 0; k0 < FD; k0 += 64) {
        #pragma unroll
        for (int f = 0; f < 4; f++) {
            int idx = f * 256 + tid;
            int m  = idx >> 4;
            int k4 = idx & 15;
            float4 v = *(const float4*)(src + (size_t)m * FD + k0 + k4 * 4);
            v.x = to_tf32(v.x); v.y = to_tf32(v.y);
            v.z = to_tf32(v.z); v.w = to_tf32(v.w);
            *(float4*)(As + m * PAROW + k4 * 4) = v;
        }
        #pragma unroll
        for (int f = 0; f < 8; f++) {
            int idx = f * 256 + tid;
            int k  = idx >> 5;
            int n4 = idx & 31;
            float4 v = *(const float4*)(W + (size_t)(k0 + k) * PD + n4 * 4);
            v.x = to_tf32(v.x); v.y = to_tf32(v.y);
            v.z = to_tf32(v.z); v.w = to_tf32(v.w);
            *(float4*)(Bs + k * PBROW + n4 * 4) = v;
        }
        __syncthreads();

        #pragma unroll
        for (int ks = 0; ks < 8; ks++) {
            int kb = ks * 8;
            uint32_t a[2][4];
            #pragma unroll
            for (int mt = 0; mt < 2; mt++) {
                const float* p = As + (rm + mt * 16 + g) * PAROW + kb + tig;
                a[mt][0] = __float_as_uint(p[0]);
                a[mt][1] = __float_as_uint(p[8 * PAROW]);
                a[mt][2] = __float_as_uint(p[4]);
                a[mt][3] = __float_as_uint(p[8 * PAROW + 4]);
            }
            #pragma unroll
            for (int nt = 0; nt < 4; nt++) {
                int nn = cn + nt * 8 + g;
                uint32_t b0 = __float_as_uint(Bs[(kb + tig) * PBROW + nn]);
                uint32_t b1 = __float_as_uint(Bs[(kb + tig + 4) * PBROW + nn]);
                #pragma unroll
                for (int mt = 0; mt < 2; mt++) {
                    asm volatile(
                        "mma.sync.aligned.m16n8k8.row.col.f32.tf32.tf32.f32 "
                        "{%0,%1,%2,%3}, {%4,%5,%6,%7}, {%8,%9}, {%0,%1,%2,%3};"
                        : "+f"(acc[mt][nt][0]), "+f"(acc[mt][nt][1]),
                          "+f"(acc[mt][nt][2]), "+f"(acc[mt][nt][3])
                        : "r"(a[mt][0]), "r"(a[mt][1]), "r"(a[mt][2]), "r"(a[mt][3]),
                          "r"(b0), "r"(b1));
                }
            }
        }
        __syncthreads();
    }

    // Epilogue: +bias, store h, fused per-column sum/sumsq (per-view)
    float cs0[4] = {}, cs1[4] = {}, cq0[4] = {}, cq1[4] = {};
    #pragma unroll
    for (int nt = 0; nt < 4; nt++) {
        int jc = cn + nt * 8 + tig * 2;
        float bb0 = bias[jc], bb1 = bias[jc + 1];
        #pragma unroll
        for (int mt = 0; mt < 2; mt++) {
            int r0 = m0 + rm + mt * 16 + g;
            int r1 = r0 + 8;
            float h0 = acc[mt][nt][0] + bb0;
            float h1 = acc[mt][nt][1] + bb1;
            float h2 = acc[mt][nt][2] + bb0;
            float h3 = acc[mt][nt][3] + bb1;
            g_h[(size_t)r0 * PD + jc]     = h0;
            g_h[(size_t)r0 * PD + jc + 1] = h1;
            g_h[(size_t)r1 * PD + jc]     = h2;
            g_h[(size_t)r1 * PD + jc + 1] = h3;
            cs0[nt] += h0 + h2;  cs1[nt] += h1 + h3;
            cq0[nt] += h0 * h0 + h2 * h2;
            cq1[nt] += h1 * h1 + h3 * h3;
        }
    }
    int v = m0 >> 12;
    #pragma unroll
    for (int nt = 0; nt < 4; nt++) {
        float a0 = cs0[nt], a1 = cs1[nt], q0 = cq0[nt], q1 = cq1[nt];
        #pragma unroll
        for (int o = 4; o < 32; o <<= 1) {
            a0 += __shfl_xor_sync(0xffffffffu, a0, o);
            a1 += __shfl_xor_sync(0xffffffffu, a1, o);
            q0 += __shfl_xor_sync(0xffffffffu, q0, o);
            q1 += __shfl_xor_sync(0xffffffffu, q1, o);
        }
        if (g == 0) {
            int jc = cn + nt * 8 + tig * 2;
            atomicAdd(&g_sum[v * PD + jc],       a0);
            atomicAdd(&g_sum[v * PD + jc + 1],   a1);
            atomicAdd(&g_sumsq[v * PD + jc],     q0);
            atomicAdd(&g_sumsq[v * PD + jc + 1], q1);
        }
    }
}

// ---------------------------------------------------------------------------
// K2: BN-normalize + cosine row-normalize; emit bf16 (RNE) zn scaled by
// sqrt(EXP_C) so the sim GEMM directly produces the ex2 argument.
// 256 threads = 8 rows x 32 lanes. Also zeroes g_rowsum.
// ---------------------------------------------------------------------------
__global__ __launch_bounds__(256) void k_norm(const float* __restrict__ gamma,
                                              const float* __restrict__ beta) {
    int row  = blockIdx.x * 8 + (threadIdx.x >> 5);
    int lane = threadIdx.x & 31;
    int c    = lane * 4;
    int v    = row >> 12;

    float4 h  = *(const float4*)(g_h + (size_t)row * PD + c);
    float4 su = *(const float4*)(g_sum + v * PD + c);
    float4 sq = *(const float4*)(g_sumsq + v * PD + c);
    float4 gm = *(const float4*)(gamma + c);
    float4 bt = *(const float4*)(beta + c);

    float z[4];
    {
        float mu, var;
        mu = su.x * (1.0f / NV); var = sq.x * (1.0f / NV) - mu * mu;
        z[0] = gm.x * (h.x - mu) * rsqrtf(var + BN_EPS) + bt.x;
        mu = su.y * (1.0f / NV); var = sq.y * (1.0f / NV) - mu * mu;
        z[1] = gm.y * (h.y - mu) * rsqrtf(var + BN_EPS) + bt.y;
        mu = su.z * (1.0f / NV); var = sq.z * (1.0f / NV) - mu * mu;
        z[2] = gm.z * (h.z - mu) * rsqrtf(var + BN_EPS) + bt.z;
        mu = su.w * (1.0f / NV); var = sq.w * (1.0f / NV) - mu * mu;
        z[3] = gm.w * (h.w - mu) * rsqrtf(var + BN_EPS) + bt.w;
    }

    float s2 = z[0] * z[0] + z[1] * z[1] + z[2] * z[2] + z[3] * z[3];
    #pragma unroll
    for (int o = 16; o > 0; o >>= 1)
        s2 += __shfl_xor_sync(0xffffffffu, s2, o);
    float inv = SQRT_EXP_C / fmaxf(sqrtf(s2), COS_EPS);

    __nv_bfloat162 p0 = __floats2bfloat162_rn(z[0] * inv, z[1] * inv);
    __nv_bfloat162 p1 = __floats2bfloat162_rn(z[2] * inv, z[3] * inv);
    uint2 st;
    st.x = *(uint32_t*)&p0;
    st.y = *(uint32_t*)&p1;
    *(uint2*)((char*)g_znb + ((size_t)row * PD + c) * 2) = st;

    if (lane == 0) g_rowsum[row] = 0.0f;
}

// ---------------------------------------------------------------------------
// K3: SYMMETRIC fused sim, bf16 mma + ldmatrix, PAIRED j-tiles per CTA.
// zn pre-scaled -> epilogue is bare ex2(acc). Column sums via reduce-scatter.
// LAST CTA (threadfence ticket) computes the final V output and resets
// stat accumulators + ticket (no separate k_final launch).
// ---------------------------------------------------------------------------
#define SPADB 136
#define SROWW (SPADB / 2)                 // 68 words per row
#define TILE_WORDS (128 * SROWW)
#define SIM_SMEM_BYTES (3 * TILE_WORDS * 4)

__device__ __forceinline__ void sim_mainloop(float acc[2][8][4],
                                             uint32_t aAddr, uint32_t bAddr) {
    const uint32_t MT_STRIDE = 16 * SROWW * 4;
    #pragma unroll
    for (int mt = 0; mt < 2; mt++)
        #pragma unroll
        for (int nt = 0; nt < 8; nt++)
            #pragma unroll
            for (int c = 0; c < 4; c++)
                acc[mt][nt][c] = 0.0f;

    #pragma unroll
    for (int ks = 0; ks < 8; ks++) {
        uint32_t kb = (uint32_t)(ks * 32);
        uint32_t a[2][4];
        ldsm_x4(a[0], aAddr + kb);
        ldsm_x4(a[1], aAddr + MT_STRIDE + kb);
        uint32_t b[4][4];
        #pragma unroll
        for (int ntp = 0; ntp < 4; ntp++)
            ldsm_x4(b[ntp], bAddr + ntp * MT_STRIDE + kb);

        #pragma unroll
        for (int ntp = 0; ntp < 4; ntp++) {
            #pragma unroll
            for (int h = 0; h < 2; h++) {
                uint32_t b0 = b[ntp][h];
                uint32_t b1 = b[ntp][h + 2];
                int nt = ntp * 2 + h;
                #pragma unroll
                for (int mt = 0; mt < 2; mt++) {
                    asm volatile(
                        "mma.sync.aligned.m16n8k16.row.col.f32.bf16.bf16.f32 "
                        "{%0,%1,%2,%3}, {%4,%5,%6,%7}, {%8,%9}, {%0,%1,%2,%3};"
                        : "+f"(acc[mt][nt][0]), "+f"(acc[mt][nt][1]),
                          "+f"(acc[mt][nt][2]), "+f"(acc[mt][nt][3])
                        : "r"(a[mt][0]), "r"(a[mt][1]), "r"(a[mt][2]), "r"(a[mt][3]),
                          "r"(b0), "r"(b1));
                }
            }
        }
    }
}

// Per-tile epilogue. Row partials accumulate into rs (deferred); column sums
// (generic/POS tiles) reduced via reduce-scatter and atomically added here.
template <bool DIAG, bool POS>
__device__ __forceinline__ void sim_tile_epi(float acc[2][8][4],
                                             int i0, int j0,
                                             int rm, int cn, int g, int tig,
                                             float rs[2][2]) {
    float cp[16];                         // cp[nt*2+h] column partials
    #pragma unroll
    for (int i = 0; i < 16; i++) cp[i] = 0.0f;

    #pragma unroll
    for (int mt = 0; mt < 2; mt++) {
        int li0 = rm + mt * 16 + g;       // local row
        int li1 = li0 + 8;
        int r0 = i0 + li0, r1 = i0 + li1;
        float s0 = 0.0f, s1 = 0.0f;
        #pragma unroll
        for (int nt = 0; nt < 8; nt++) {
            int lj = cn + nt * 8 + tig * 2;
            float v0 = ex2(acc[mt][nt][0]);
            float v1 = ex2(acc[mt][nt][1]);
            float v2 = ex2(acc[mt][nt][2]);
            float v3 = ex2(acc[mt][nt][3]);
            if (DIAG) {
                if (li0 == lj)     v0 = 0.0f;
                if (li0 == lj + 1) v1 = 0.0f;
                if (li1 == lj)     v2 = 0.0f;
                if (li1 == lj + 1) v3 = 0.0f;
            }
            if (POS) {                    // partner pairs lie on local diagonal
                if (li0 == lj)     { g_pos[r0] = v0; g_pos[j0 + lj]     = v0; }
                if (li0 == lj + 1) { g_pos[r0] = v1; g_pos[j0 + lj + 1] = v1; }
                if (li1 == lj)     { g_pos[r1] = v2; g_pos[j0 + lj]     = v2; }
                if (li1 == lj + 1) { g_pos[r1] = v3; g_pos[j0 + lj + 1] = v3; }
            }
            s0 += v0 + v1;
            s1 += v2 + v3;
            if (!DIAG) { cp[nt * 2] += v0 + v2; cp[nt * 2 + 1] += v1 + v3; }
        }
        rs[mt][0] += s0;
        rs[mt][1] += s1;
    }

    if (!DIAG) {
        // Reduce-scatter over the 8 g-lanes (masks 4,8,16). Step1 keeps index
        // 2j+b0; step2 -> 4j+2b1+b0; step3 -> 8j+g. Lane g owns {g, 8+g}.
        int b0 = g & 1, b1 = (g >> 1) & 1, b2 = (g >> 2) & 1;
        float w[8];
        #pragma unroll
        for (int j = 0; j < 8; j++) {
            float keep = b0 ? cp[2 * j + 1] : cp[2 * j];
            float send = b0 ? cp[2 * j]     : cp[2 * j + 1];
            w[j] = keep + __shfl_xor_sync(0xffffffffu, send, 4);
        }
        float u[4];
        #pragma unroll
        for (int j = 0; j < 4; j++) {
            float keep = b1 ? w[2 * j + 1] : w[2 * j];
            float send = b1 ? w[2 * j]     : w[2 * j + 1];
            u[j] = keep + __shfl_xor_sync(0xffffffffu, send, 8);
        }
        float t[2];
        #pragma unroll
        for (int j = 0; j < 2; j++) {
            float keep = b2 ? u[2 * j + 1] : u[2 * j];
            float send = b2 ? u[2 * j]     : u[2 * j + 1];
            t[j] = keep + __shfl_xor_sync(0xffffffffu, send, 16);
        }
        #pragma unroll
        for (int j = 0; j < 2; j++) {
            int i = 8 * j + g;            // owner index
            atomicAdd(&g_rowsum[j0 + cn + (i >> 1) * 8 + tig * 2 + (i & 1)], t[j]);
        }
    }
}

__global__ __launch_bounds__(256, 2) void k_sim_mma(float* __restrict__ out) {
    extern __shared__ uint32_t smw[];
    __shared__ int s_last;
    int tid = threadIdx.x;
    int lane = tid & 31, wid = tid >> 5;

    // decode blockIdx.x -> (bi, pair p); row bi has ceil((NB-bi)/2) pairs
    int T = blockIdx.x, bi = 0;
    for (;;) {
        int np = (NB + 1 - bi) >> 1;
        if (T < np) break;
        T -= np; bi++;
    }
    int bj0 = bi + 2 * T;
    int bj1 = bj0 + 1;
    bool has2 = (bj1 < NB);
    int i0  = bi * 128;
    int j00 = bj0 * 128;
    int j01 = bj1 * 128;

    uint32_t smem0 = (uint32_t)__cvta_generic_to_shared(smw);

    // Load A + B0 (+B1): each tile row = 256 B = 16 uint4; 2048 uint4/tile.
    #pragma unroll
    for (int f = 0; f < 8; f++) {
        int idx = f * 256 + tid;
        int m  = idx >> 4;
        int c4 = idx & 15;
        uint32_t soff = (uint32_t)((m * SROWW + c4 * 4) * 4);
        uint4 va = *(const uint4*)((const char*)g_znb + ((size_t)(i0 + m) * PD) * 2 + c4 * 16);
        *(uint4*)((char*)smw + soff) = va;
        uint4 vb = *(const uint4*)((const char*)g_znb + ((size_t)(j00 + m) * PD) * 2 + c4 * 16);
        *(uint4*)((char*)smw + TILE_WORDS * 4 + soff) = vb;
    }
    if (has2) {
        #pragma unroll
        for (int f = 0; f < 8; f++) {
            int idx = f * 256 + tid;
            int m  = idx >> 4;
            int c4 = idx & 15;
            uint32_t soff = (uint32_t)((m * SROWW + c4 * 4) * 4);
            uint4 vc = *(const uint4*)((const char*)g_znb + ((size_t)(j01 + m) * PD) * 2 + c4 * 16);
            *(uint4*)((char*)smw + 2 * TILE_WORDS * 4 + soff) = vc;
        }
    }
    __syncthreads();

    int g = lane >> 2, tig = lane & 3;
    int rm = (wid & 3) * 32;              // warp row base (i-local)
    int cn = (wid >> 2) * 64;             // warp col base (j-local)

    int frow = ((lane >> 3) & 1) * 8 + (lane & 7);
    int fkw  = ((lane >> 4) & 1) * 4;
    uint32_t aAddr  = smem0 + (uint32_t)(((rm + frow) * SROWW + fkw) * 4);
    uint32_t b0Addr = smem0 + (uint32_t)(TILE_WORDS * 4)
                    + (uint32_t)(((cn + frow) * SROWW + fkw) * 4);
    uint32_t b1Addr = b0Addr + (uint32_t)(TILE_WORDS * 4);

    float acc[2][8][4];
    float rs[2][2] = {};                  // deferred row partial sums

    // Tile 0 (may be DIAG at p==0, or POS at bj0-bi==32)
    sim_mainloop(acc, aAddr, b0Addr);
    if (bj0 == bi)
        sim_tile_epi<true, false>(acc, i0, j00, rm, cn, g, tig, rs);
    else if (bj0 == (bi ^ 32))
        sim_tile_epi<false, true>(acc, i0, j00, rm, cn, g, tig, rs);
    else
        sim_tile_epi<false, false>(acc, i0, j00, rm, cn, g, tig, rs);

    // Tile 1 (always generic: bj1-bi odd, != 0 and != 32)
    if (has2) {
        sim_mainloop(acc, aAddr, b1Addr);
        sim_tile_epi<false, false>(acc, i0, j01, rm, cn, g, tig, rs);
    }

    // Deferred row sums (rows of bi tile; combined over both tiles)
    #pragma unroll
    for (int mt = 0; mt < 2; mt++) {
        float s0 = rs[mt][0], s1 = rs[mt][1];
        s0 += __shfl_xor_sync(0xffffffffu, s0, 1);
        s0 += __shfl_xor_sync(0xffffffffu, s0, 2);
        s1 += __shfl_xor_sync(0xffffffffu, s1, 1);
        s1 += __shfl_xor_sync(0xffffffffu, s1, 2);
        if (tig == 0) {
            int r0 = i0 + rm + mt * 16 + g;
            atomicAdd(&g_rowsum[r0], s0);
            atomicAdd(&g_rowsum[r0 + 8], s1);
        }
    }

    // ---- last-CTA finalization (replaces separate k_final launch) ----
    __threadfence();                      // order this CTA's writes (all threads)
    __syncthreads();                      // all fences executed before ticket
    if (tid == 0)
        s_last = (atomicAdd(&g_ctr, 1) == N_SIM_CTAS - 1);
    __syncthreads();
    if (s_last) {
        __threadfence();                  // acquire: see all CTAs' results
        #pragma unroll
        for (int f = 0; f < TWON / 256; f++) {
            int i = f * 256 + tid;
            out[i] = LN2F * (__log2f(g_rowsum[i]) - __log2f(g_pos[i]));
        }
        // reset state for next graph replay
        g_sum[tid]   = 0.0f;              // 256 threads cover 2*PD
        g_sumsq[tid] = 0.0f;
        if (tid == 0) g_ctr = 0;
    }
}

// ---------------------------------------------------------------------------
extern "C" void kernel_launch(void* const* d_in, const int* in_sizes, int n_in,
                              void* d_out, int out_size) {
    const float* x     = (const float*)d_in[0];
    const float* xt    = (const float*)d_in[1];
    const float* W     = (const float*)d_in[2];
    const float* bias  = (const float*)d_in[3];
    const float* gamma = (const float*)d_in[4];
    const float* beta  = (const float*)d_in[5];
    float* out = (float*)d_out;

    cudaFuncSetAttribute(k_sim_mma, cudaFuncAttributeMaxDynamicSharedMemorySize,
                         SIM_SMEM_BYTES);
    cudaFuncSetAttribute(k_proj_mma, cudaFuncAttributeMaxDynamicSharedMemorySize,
                         PROJ_SMEM);

    k_proj_mma<<<TWON / 64, 256, PROJ_SMEM>>>(x, xt, W, bias);
    k_norm <<<TWON / 8, 256>>>(gamma, beta);
    k_sim_mma<<<N_SIM_CTAS, 256, SIM_SMEM_BYTES>>>(out);
}

// round 15
// speedup vs baseline: 1.2869x; 1.2869x over previous
#include <cuda_runtime.h>
#include <cuda_bf16.h>
#include <math.h>
#include <cstdint>

// Problem constants (shapes fixed by setup_inputs)
#define NV    4096          // batch per view
#define TWON  8192          // 2N rows total
#define FD    512           // feature dim
#define PD    128           // projection dim
#define NB    (TWON / 128)  // 64 tile-blocks per dimension
#define BN_EPS  1e-5f
#define COS_EPS 1e-8f
// exp(sim/T) = 2^(sim * 10 * log2(e));  zn is pre-scaled by sqrt of this
#define SQRT_EXP_C 3.7982825f          // sqrt(14.426950408889634)
#define LN2F 0.69314718056f

// Scratch (no allocations allowed -> __device__ globals)
__device__ float g_h[TWON * PD];               // projected pre-BN activations
__device__ __nv_bfloat16 g_znb[TWON * PD];     // sqrt(EXP_C)-scaled normalized rows
__device__ float g_sum[2 * PD];                // per-view per-col sum (zeroed by k_final)
__device__ float g_sumsq[2 * PD];              // per-view per-col sumsq (zeroed by k_final)
__device__ float g_rowsum[TWON];               // sum_j S_ij (diag excluded)
__device__ float g_pos[TWON];                  // S_{i, i^NV}

// RNA-rounded tf32 (unbiased)
__device__ __forceinline__ float to_tf32(float x) {
    uint32_t u;
    asm("cvt.rna.tf32.f32 %0, %1;" : "=r"(u) : "f"(x));
    return __uint_as_float(u);
}

__device__ __forceinline__ float ex2(float x) {
    float y;
    asm("ex2.approx.ftz.f32 %0, %1;" : "=f"(y) : "f"(x));
    return y;
}

__device__ __forceinline__ void ldsm_x4(uint32_t* r, uint32_t addr) {
    asm volatile("ldmatrix.sync.aligned.m8n8.x4.shared.b16 {%0,%1,%2,%3}, [%4];"
                 : "=r"(r[0]), "=r"(r[1]), "=r"(r[2]), "=r"(r[3]) : "r"(addr));
}

// ---------------------------------------------------------------------------
// K1: h = concat(x, xt) @ W + b via tf32 mma.sync, fused BN column stats.
// CTA tile 32x128 (grid 256 -> covers all SMs), BK=64, 256 threads;
// 8 warps each own 32m x 16n (acc[2][2][4]).
// ---------------------------------------------------------------------------
#define PAROW 68
#define PBROW 136
#define PROJ_SMEM ((32 * PAROW + 64 * PBROW) * 4)

__global__ __launch_bounds__(256) void k_proj_mma(const float* __restrict__ x,
                                                  const float* __restrict__ xt,
                                                  const float* __restrict__ W,
                                                  const float* __restrict__ bias) {
    extern __shared__ float ps[];
    float* As = ps;                       // [32][PAROW]
    float* Bs = ps + 32 * PAROW;          // [64][PBROW]  ([k][n])
    int tid = threadIdx.x;
    int lane = tid & 31, wid = tid >> 5;
    int g = lane >> 2, tig = lane & 3;
    int m0 = blockIdx.x * 32;
    const float* src = (m0 < NV) ? (x + (size_t)m0 * FD)
                                 : (xt + (size_t)(m0 - NV) * FD);
    int cn = wid * 16;                    // warp col base (n-local), 8 warps x 16

    float acc[2][2][4] = {};

    for (int k0 = 0; k0 < FD; k0 += 64) {
        // A chunk: 32 rows x 64 k = 512 float4
        #pragma unroll
        for (int f = 0; f < 2; f++) {
            int idx = f * 256 + tid;
            int m  = idx >> 4;            // 0..31
            int k4 = idx & 15;
            float4 v = *(const float4*)(src + (size_t)m * FD + k0 + k4 * 4);
            v.x = to_tf32(v.x); v.y = to_tf32(v.y);
            v.z = to_tf32(v.z); v.w = to_tf32(v.w);
            *(float4*)(As + m * PAROW + k4 * 4) = v;
        }
        // W chunk: 64 k x 128 n = 2048 float4
        #pragma unroll
        for (int f = 0; f < 8; f++) {
            int idx = f * 256 + tid;
            int k  = idx >> 5;
            int n4 = idx & 31;
            float4 v = *(const float4*)(W + (size_t)(k0 + k) * PD + n4 * 4);
            v.x = to_tf32(v.x); v.y = to_tf32(v.y);
            v.z = to_tf32(v.z); v.w = to_tf32(v.w);
            *(float4*)(Bs + k * PBROW + n4 * 4) = v;
        }
        __syncthreads();

        #pragma unroll
        for (int ks = 0; ks < 8; ks++) {
            int kb = ks * 8;
            uint32_t a[2][4];
            #pragma unroll
            for (int mt = 0; mt < 2; mt++) {
                const float* p = As + (mt * 16 + g) * PAROW + kb + tig;
                a[mt][0] = __float_as_uint(p[0]);
                a[mt][1] = __float_as_uint(p[8 * PAROW]);
                a[mt][2] = __float_as_uint(p[4]);
                a[mt][3] = __float_as_uint(p[8 * PAROW + 4]);
            }
            #pragma unroll
            for (int nt = 0; nt < 2; nt++) {
                int nn = cn + nt * 8 + g;
                uint32_t b0 = __float_as_uint(Bs[(kb + tig) * PBROW + nn]);
                uint32_t b1 = __float_as_uint(Bs[(kb + tig + 4) * PBROW + nn]);
                #pragma unroll
                for (int mt = 0; mt < 2; mt++) {
                    asm volatile(
                        "mma.sync.aligned.m16n8k8.row.col.f32.tf32.tf32.f32 "
                        "{%0,%1,%2,%3}, {%4,%5,%6,%7}, {%8,%9}, {%0,%1,%2,%3};"
                        : "+f"(acc[mt][nt][0]), "+f"(acc[mt][nt][1]),
                          "+f"(acc[mt][nt][2]), "+f"(acc[mt][nt][3])
                        : "r"(a[mt][0]), "r"(a[mt][1]), "r"(a[mt][2]), "r"(a[mt][3]),
                          "r"(b0), "r"(b1));
                }
            }
        }
        __syncthreads();
    }

    // Epilogue: +bias, store h, fused per-column sum/sumsq (per-view)
    float cs0[2] = {}, cs1[2] = {}, cq0[2] = {}, cq1[2] = {};
    #pragma unroll
    for (int nt = 0; nt < 2; nt++) {
        int jc = cn + nt * 8 + tig * 2;
        float bb0 = bias[jc], bb1 = bias[jc + 1];
        #pragma unroll
        for (int mt = 0; mt < 2; mt++) {
            int r0 = m0 + mt * 16 + g;
            int r1 = r0 + 8;
            float h0 = acc[mt][nt][0] + bb0;
            float h1 = acc[mt][nt][1] + bb1;
            float h2 = acc[mt][nt][2] + bb0;
            float h3 = acc[mt][nt][3] + bb1;
            g_h[(size_t)r0 * PD + jc]     = h0;
            g_h[(size_t)r0 * PD + jc + 1] = h1;
            g_h[(size_t)r1 * PD + jc]     = h2;
            g_h[(size_t)r1 * PD + jc + 1] = h3;
            cs0[nt] += h0 + h2;  cs1[nt] += h1 + h3;
            cq0[nt] += h0 * h0 + h2 * h2;
            cq1[nt] += h1 * h1 + h3 * h3;
        }
    }
    int v = m0 >> 12;
    #pragma unroll
    for (int nt = 0; nt < 2; nt++) {
        float a0 = cs0[nt], a1 = cs1[nt], q0 = cq0[nt], q1 = cq1[nt];
        #pragma unroll
        for (int o = 4; o < 32; o <<= 1) {
            a0 += __shfl_xor_sync(0xffffffffu, a0, o);
            a1 += __shfl_xor_sync(0xffffffffu, a1, o);
            q0 += __shfl_xor_sync(0xffffffffu, q0, o);
            q1 += __shfl_xor_sync(0xffffffffu, q1, o);
        }
        if (g == 0) {
            int jc = cn + nt * 8 + tig * 2;
            atomicAdd(&g_sum[v * PD + jc],       a0);
            atomicAdd(&g_sum[v * PD + jc + 1],   a1);
            atomicAdd(&g_sumsq[v * PD + jc],     q0);
            atomicAdd(&g_sumsq[v * PD + jc + 1], q1);
        }
    }
}

// ---------------------------------------------------------------------------
// K2: BN-normalize + cosine row-normalize; emit bf16 (RNE) zn scaled by
// sqrt(EXP_C) so the sim GEMM directly produces the ex2 argument.
// 256 threads = 8 rows x 32 lanes. Also zeroes g_rowsum.
// ---------------------------------------------------------------------------
__global__ __launch_bounds__(256) void k_norm(const float* __restrict__ gamma,
                                              const float* __restrict__ beta) {
    int row  = blockIdx.x * 8 + (threadIdx.x >> 5);
    int lane = threadIdx.x & 31;
    int c    = lane * 4;
    int v    = row >> 12;

    float4 h  = *(const float4*)(g_h + (size_t)row * PD + c);
    float4 su = *(const float4*)(g_sum + v * PD + c);
    float4 sq = *(const float4*)(g_sumsq + v * PD + c);
    float4 gm = *(const float4*)(gamma + c);
    float4 bt = *(const float4*)(beta + c);

    float z[4];
    {
        float mu, var;
        mu = su.x * (1.0f / NV); var = sq.x * (1.0f / NV) - mu * mu;
        z[0] = gm.x * (h.x - mu) * rsqrtf(var + BN_EPS) + bt.x;
        mu = su.y * (1.0f / NV); var = sq.y * (1.0f / NV) - mu * mu;
        z[1] = gm.y * (h.y - mu) * rsqrtf(var + BN_EPS) + bt.y;
        mu = su.z * (1.0f / NV); var = sq.z * (1.0f / NV) - mu * mu;
        z[2] = gm.z * (h.z - mu) * rsqrtf(var + BN_EPS) + bt.z;
        mu = su.w * (1.0f / NV); var = sq.w * (1.0f / NV) - mu * mu;
        z[3] = gm.w * (h.w - mu) * rsqrtf(var + BN_EPS) + bt.w;
    }

    float s2 = z[0] * z[0] + z[1] * z[1] + z[2] * z[2] + z[3] * z[3];
    #pragma unroll
    for (int o = 16; o > 0; o >>= 1)
        s2 += __shfl_xor_sync(0xffffffffu, s2, o);
    float inv = SQRT_EXP_C / fmaxf(sqrtf(s2), COS_EPS);

    __nv_bfloat162 p0 = __floats2bfloat162_rn(z[0] * inv, z[1] * inv);
    __nv_bfloat162 p1 = __floats2bfloat162_rn(z[2] * inv, z[3] * inv);
    uint2 st;
    st.x = *(uint32_t*)&p0;
    st.y = *(uint32_t*)&p1;
    *(uint2*)((char*)g_znb + ((size_t)row * PD + c) * 2) = st;

    if (lane == 0) g_rowsum[row] = 0.0f;
}

// ---------------------------------------------------------------------------
// K3: SYMMETRIC fused sim, bf16 mma + ldmatrix, PAIRED j-tiles per CTA.
// zn pre-scaled -> epilogue is bare ex2(acc). Column sums via reduce-scatter.
// (R13 structure — NO in-kernel finalization: the per-CTA __threadfence of
// the fused variant flushes L1D on Blackwell and cost 14us. Keep k_final.)
// ---------------------------------------------------------------------------
#define SPADB 136
#define SROWW (SPADB / 2)                 // 68 words per row
#define TILE_WORDS (128 * SROWW)
#define SIM_SMEM_BYTES (3 * TILE_WORDS * 4)

__device__ __forceinline__ void sim_mainloop(float acc[2][8][4],
                                             uint32_t aAddr, uint32_t bAddr) {
    const uint32_t MT_STRIDE = 16 * SROWW * 4;
    #pragma unroll
    for (int mt = 0; mt < 2; mt++)
        #pragma unroll
        for (int nt = 0; nt < 8; nt++)
            #pragma unroll
            for (int c = 0; c < 4; c++)
                acc[mt][nt][c] = 0.0f;

    #pragma unroll
    for (int ks = 0; ks < 8; ks++) {
        uint32_t kb = (uint32_t)(ks * 32);
        uint32_t a[2][4];
        ldsm_x4(a[0], aAddr + kb);
        ldsm_x4(a[1], aAddr + MT_STRIDE + kb);
        uint32_t b[4][4];
        #pragma unroll
        for (int ntp = 0; ntp < 4; ntp++)
            ldsm_x4(b[ntp], bAddr + ntp * MT_STRIDE + kb);

        #pragma unroll
        for (int ntp = 0; ntp < 4; ntp++) {
            #pragma unroll
            for (int h = 0; h < 2; h++) {
                uint32_t b0 = b[ntp][h];
                uint32_t b1 = b[ntp][h + 2];
                int nt = ntp * 2 + h;
                #pragma unroll
                for (int mt = 0; mt < 2; mt++) {
                    asm volatile(
                        "mma.sync.aligned.m16n8k16.row.col.f32.bf16.bf16.f32 "
                        "{%0,%1,%2,%3}, {%4,%5,%6,%7}, {%8,%9}, {%0,%1,%2,%3};"
                        : "+f"(acc[mt][nt][0]), "+f"(acc[mt][nt][1]),
                          "+f"(acc[mt][nt][2]), "+f"(acc[mt][nt][3])
                        : "r"(a[mt][0]), "r"(a[mt][1]), "r"(a[mt][2]), "r"(a[mt][3]),
                          "r"(b0), "r"(b1));
                }
            }
        }
    }
}

// Per-tile epilogue. Row partials accumulate into rs (deferred); column sums
// (generic/POS tiles) reduced via reduce-scatter and atomically added here.
template <bool DIAG, bool POS>
__device__ __forceinline__ void sim_tile_epi(float acc[2][8][4],
                                             int i0, int j0,
                                             int rm, int cn, int g, int tig,
                                             float rs[2][2]) {
    float cp[16];                         // cp[nt*2+h] column partials
    #pragma unroll
    for (int i = 0; i < 16; i++) cp[i] = 0.0f;

    #pragma unroll
    for (int mt = 0; mt < 2; mt++) {
        int li0 = rm + mt * 16 + g;       // local row
        int li1 = li0 + 8;
        int r0 = i0 + li0, r1 = i0 + li1;
        float s0 = 0.0f, s1 = 0.0f;
        #pragma unroll
        for (int nt = 0; nt < 8; nt++) {
            int lj = cn + nt * 8 + tig * 2;
            float v0 = ex2(acc[mt][nt][0]);
            float v1 = ex2(acc[mt][nt][1]);
            float v2 = ex2(acc[mt][nt][2]);
            float v3 = ex2(acc[mt][nt][3]);
            if (DIAG) {
                if (li0 == lj)     v0 = 0.0f;
                if (li0 == lj + 1) v1 = 0.0f;
                if (li1 == lj)     v2 = 0.0f;
                if (li1 == lj + 1) v3 = 0.0f;
            }
            if (POS) {                    // partner pairs lie on local diagonal
                if (li0 == lj)     { g_pos[r0] = v0; g_pos[j0 + lj]     = v0; }
                if (li0 == lj + 1) { g_pos[r0] = v1; g_pos[j0 + lj + 1] = v1; }
                if (li1 == lj)     { g_pos[r1] = v2; g_pos[j0 + lj]     = v2; }
                if (li1 == lj + 1) { g_pos[r1] = v3; g_pos[j0 + lj + 1] = v3; }
            }
            s0 += v0 + v1;
            s1 += v2 + v3;
            if (!DIAG) { cp[nt * 2] += v0 + v2; cp[nt * 2 + 1] += v1 + v3; }
        }
        rs[mt][0] += s0;
        rs[mt][1] += s1;
    }

    if (!DIAG) {
        // Reduce-scatter over the 8 g-lanes (masks 4,8,16). Step1 keeps index
        // 2j+b0; step2 -> 4j+2b1+b0; step3 -> 8j+g. Lane g owns {g, 8+g}.
        int b0 = g & 1, b1 = (g >> 1) & 1, b2 = (g >> 2) & 1;
        float w[8];
        #pragma unroll
        for (int j = 0; j < 8; j++) {
            float keep = b0 ? cp[2 * j + 1] : cp[2 * j];
            float send = b0 ? cp[2 * j]     : cp[2 * j + 1];
            w[j] = keep + __shfl_xor_sync(0xffffffffu, send, 4);
        }
        float u[4];
        #pragma unroll
        for (int j = 0; j < 4; j++) {
            float keep = b1 ? w[2 * j + 1] : w[2 * j];
            float send = b1 ? w[2 * j]     : w[2 * j + 1];
            u[j] = keep + __shfl_xor_sync(0xffffffffu, send, 8);
        }
        float t[2];
        #pragma unroll
        for (int j = 0; j < 2; j++) {
            float keep = b2 ? u[2 * j + 1] : u[2 * j];
            float send = b2 ? u[2 * j]     : u[2 * j + 1];
            t[j] = keep + __shfl_xor_sync(0xffffffffu, send, 16);
        }
        #pragma unroll
        for (int j = 0; j < 2; j++) {
            int i = 8 * j + g;            // owner index
            atomicAdd(&g_rowsum[j0 + cn + (i >> 1) * 8 + tig * 2 + (i & 1)], t[j]);
        }
    }
}

__global__ __launch_bounds__(256, 2) void k_sim_mma() {
    extern __shared__ uint32_t smw[];
    int tid = threadIdx.x;
    int lane = tid & 31, wid = tid >> 5;

    // decode blockIdx.x -> (bi, pair p); row bi has ceil((NB-bi)/2) pairs
    int T = blockIdx.x, bi = 0;
    for (;;) {
        int np = (NB + 1 - bi) >> 1;
        if (T < np) break;
        T -= np; bi++;
    }
    int bj0 = bi + 2 * T;
    int bj1 = bj0 + 1;
    bool has2 = (bj1 < NB);
    int i0  = bi * 128;
    int j00 = bj0 * 128;
    int j01 = bj1 * 128;

    uint32_t smem0 = (uint32_t)__cvta_generic_to_shared(smw);

    // Load A + B0 (+B1): each tile row = 256 B = 16 uint4; 2048 uint4/tile.
    #pragma unroll
    for (int f = 0; f < 8; f++) {
        int idx = f * 256 + tid;
        int m  = idx >> 4;
        int c4 = idx & 15;
        uint32_t soff = (uint32_t)((m * SROWW + c4 * 4) * 4);
        uint4 va = *(const uint4*)((const char*)g_znb + ((size_t)(i0 + m) * PD) * 2 + c4 * 16);
        *(uint4*)((char*)smw + soff) = va;
        uint4 vb = *(const uint4*)((const char*)g_znb + ((size_t)(j00 + m) * PD) * 2 + c4 * 16);
        *(uint4*)((char*)smw + TILE_WORDS * 4 + soff) = vb;
    }
    if (has2) {
        #pragma unroll
        for (int f = 0; f < 8; f++) {
            int idx = f * 256 + tid;
            int m  = idx >> 4;
            int c4 = idx & 15;
            uint32_t soff = (uint32_t)((m * SROWW + c4 * 4) * 4);
            uint4 vc = *(const uint4*)((const char*)g_znb + ((size_t)(j01 + m) * PD) * 2 + c4 * 16);
            *(uint4*)((char*)smw + 2 * TILE_WORDS * 4 + soff) = vc;
        }
    }
    __syncthreads();

    int g = lane >> 2, tig = lane & 3;
    int rm = (wid & 3) * 32;              // warp row base (i-local)
    int cn = (wid >> 2) * 64;             // warp col base (j-local)

    int frow = ((lane >> 3) & 1) * 8 + (lane & 7);
    int fkw  = ((lane >> 4) & 1) * 4;
    uint32_t aAddr  = smem0 + (uint32_t)(((rm + frow) * SROWW + fkw) * 4);
    uint32_t b0Addr = smem0 + (uint32_t)(TILE_WORDS * 4)
                    + (uint32_t)(((cn + frow) * SROWW + fkw) * 4);
    uint32_t b1Addr = b0Addr + (uint32_t)(TILE_WORDS * 4);

    float acc[2][8][4];
    float rs[2][2] = {};                  // deferred row partial sums

    // Tile 0 (may be DIAG at p==0, or POS at bj0-bi==32)
    sim_mainloop(acc, aAddr, b0Addr);
    if (bj0 == bi)
        sim_tile_epi<true, false>(acc, i0, j00, rm, cn, g, tig, rs);
    else if (bj0 == (bi ^ 32))
        sim_tile_epi<false, true>(acc, i0, j00, rm, cn, g, tig, rs);
    else
        sim_tile_epi<false, false>(acc, i0, j00, rm, cn, g, tig, rs);

    // Tile 1 (always generic: bj1-bi odd, != 0 and != 32)
    if (has2) {
        sim_mainloop(acc, aAddr, b1Addr);
        sim_tile_epi<false, false>(acc, i0, j01, rm, cn, g, tig, rs);
    }

    // Deferred row sums (rows of bi tile; combined over both tiles)
    #pragma unroll
    for (int mt = 0; mt < 2; mt++) {
        float s0 = rs[mt][0], s1 = rs[mt][1];
        s0 += __shfl_xor_sync(0xffffffffu, s0, 1);
        s0 += __shfl_xor_sync(0xffffffffu, s0, 2);
        s1 += __shfl_xor_sync(0xffffffffu, s1, 1);
        s1 += __shfl_xor_sync(0xffffffffu, s1, 2);
        if (tig == 0) {
            int r0 = i0 + rm + mt * 16 + g;
            atomicAdd(&g_rowsum[r0], s0);
            atomicAdd(&g_rowsum[r0 + 8], s1);
        }
    }
}

// ---------------------------------------------------------------------------
// K4: V_i = ln2 * (lg2(rowsum_i) - lg2(pos_i)) via fast MUFU lg2.
// Also re-zeroes BN stat accumulators for the next invocation.
// ---------------------------------------------------------------------------
__global__ void k_final(float* __restrict__ out) {
    int i = blockIdx.x * 256 + threadIdx.x;
    if (i < TWON)
        out[i] = LN2F * (__log2f(g_rowsum[i]) - __log2f(g_pos[i]));
    if (blockIdx.x == 0) {
        g_sum[threadIdx.x]   = 0.0f;      // 256 threads cover 2*PD = 256
        g_sumsq[threadIdx.x] = 0.0f;
    }
}

// ---------------------------------------------------------------------------
extern "C" void kernel_launch(void* const* d_in, const int* in_sizes, int n_in,
                              void* d_out, int out_size) {
    const float* x     = (const float*)d_in[0];
    const float* xt    = (const float*)d_in[1];
    const float* W     = (const float*)d_in[2];
    const float* bias  = (const float*)d_in[3];
    const float* gamma = (const float*)d_in[4];
    const float* beta  = (const float*)d_in[5];
    float* out = (float*)d_out;

    cudaFuncSetAttribute(k_sim_mma, cudaFuncAttributeMaxDynamicSharedMemorySize,
                         SIM_SMEM_BYTES);
    cudaFuncSetAttribute(k_proj_mma, cudaFuncAttributeMaxDynamicSharedMemorySize,
                         PROJ_SMEM);

    // grid = sum over bi of ceil((NB-bi)/2) = 1056
    int n_ctas = 0;
    for (int b = 0; b < NB; b++) n_ctas += (NB + 1 - b) >> 1;

    k_proj_mma<<<TWON / 32, 256, PROJ_SMEM>>>(x, xt, W, bias);
    k_norm <<<TWON / 8, 256>>>(gamma, beta);
    k_sim_mma<<<n_ctas, 256, SIM_SMEM_BYTES>>>();
    k_final<<<32, 256>>>(out);
}